// round 9
// baseline (speedup 1.0000x reference)
#include <cuda_runtime.h>
#include <cuda_bf16.h>
#include <cstdint>

#define BSZ 8
#define CDIM 64
#define HDIM 128
#define WDIM 128
#define HID 128

// smem strides (bf16 elems), padding keeps ldmatrix / column access conflict-light
#define LDA1 136   // K1 A: [c][w], 64 rows
#define LDB1 72    // K1 B: [o][c], 128 rows
#define LDS1 136   // K1 staging [o][w] bf16
#define LDA3 136   // K3 A: [o][w], 128 rows
#define LDB3 136   // K3 B: [c][o], 64 rows
#define LDP  132   // K3 fp32 staging [c][w]
#define LDK2 136   // K2 planes [h][w] bf16

// ---- scratch (device globals; allocation-free) ----
__device__ __nv_bfloat16 g_xp[BSZ*HDIM*HID*WDIM];  // x_proj [b][h][o][w] bf16
__device__ __nv_bfloat16 g_hs[BSZ*HDIM*HID*WDIM];  // h_sum  [b][h][o][w] bf16
__device__ __align__(16) __nv_bfloat16 g_WinP[HID*LDB1];    // [o][c] padded
__device__ __align__(16) __nv_bfloat16 g_WoutP[CDIM*LDB3];  // [c][o] padded
__device__ float g_At[HID];

__device__ __forceinline__ uint32_t smem_u32(const void* p) {
    return (uint32_t)__cvta_generic_to_shared(p);
}

// ---- ldmatrix / mma.sync wrappers (sm_80-portable) ----
__device__ __forceinline__ void ldsm_x4_trans(uint32_t* r, uint32_t a) {
    asm volatile("ldmatrix.sync.aligned.m8n8.x4.trans.shared.b16 {%0,%1,%2,%3}, [%4];"
        : "=r"(r[0]), "=r"(r[1]), "=r"(r[2]), "=r"(r[3]) : "r"(a));
}
__device__ __forceinline__ void ldsm_x4(uint32_t* r, uint32_t a) {
    asm volatile("ldmatrix.sync.aligned.m8n8.x4.shared.b16 {%0,%1,%2,%3}, [%4];"
        : "=r"(r[0]), "=r"(r[1]), "=r"(r[2]), "=r"(r[3]) : "r"(a));
}
__device__ __forceinline__ void mma_bf16(float* d, const uint32_t* a, const uint32_t* b) {
    asm volatile("mma.sync.aligned.m16n8k16.row.col.f32.bf16.bf16.f32 "
        "{%0,%1,%2,%3}, {%4,%5,%6,%7}, {%8,%9}, {%0,%1,%2,%3};"
        : "+f"(d[0]), "+f"(d[1]), "+f"(d[2]), "+f"(d[3])
        : "r"(a[0]), "r"(a[1]), "r"(a[2]), "r"(a[3]), "r"(b[0]), "r"(b[1]));
}

// ---- bilinear prior 32->128, align_corners, clip ----
__device__ __forceinline__ float prior_at(const float* __restrict__ prior,
                                          int b, int h, int w) {
    const float s = 31.0f / 127.0f;
    float ys = h * s, xs = w * s;
    int y0 = (int)ys, x0 = (int)xs;
    int y1 = min(y0 + 1, 31), x1 = min(x0 + 1, 31);
    float wy = ys - (float)y0, wx = xs - (float)x0;
    const float* p = prior + b * 1024;
    float p00 = p[y0*32+x0], p01 = p[y0*32+x1];
    float p10 = p[y1*32+x0], p11 = p[y1*32+x1];
    float top = p00 + (p01 - p00) * wx;
    float bot = p10 + (p11 - p10) * wx;
    float v = top + (bot - top) * wy;
    return fminf(1.0f, fmaxf(-1.0f, v));
}

// ---- K0: weights -> padded bf16 layouts + tanh(A) ----
__global__ void k_setup(const float* __restrict__ Win,
                        const float* __restrict__ Wout,
                        const float* __restrict__ A) {
    int i = blockIdx.x * 256 + threadIdx.x;
    if (i < 8192) {
        int o = i >> 6, c = i & 63;
        g_WinP[o * LDB1 + c] = __float2bfloat16(Win[o * 64 + c]);
        int cc = i >> 7, oo = i & 127;
        g_WoutP[cc * LDB3 + oo] = __float2bfloat16(Wout[cc * 128 + oo]);
    }
    if (i < 128) g_At[i] = tanhf(A[i]);
}

// ---- K1: per-(b,h): x_proj = F_mod @ Win^T + b_in (HMMA) ----
// smem: sA [64c][136w] bf16 17408B @0 ; sB [128o][72c] bf16 18432B @17408
//       sPb [128o][136w] bf16 34816B overlays sA after MMA. total 35840B.
__global__ __launch_bounds__(256) void k1(
    const float* __restrict__ x, const float* __restrict__ prior,
    const float* __restrict__ b_in, const float* __restrict__ alpha_p)
{
    extern __shared__ __align__(16) char smch[];
    __nv_bfloat16* sA = (__nv_bfloat16*)smch;
    __nv_bfloat16* sB = (__nv_bfloat16*)(smch + 17408);
    __nv_bfloat16* sPb = (__nv_bfloat16*)smch;
    __shared__ float s_pr[128], s_bin[128];

    const int t = threadIdx.x;
    const int wid = t >> 5, lid = t & 31;
    const int h = blockIdx.x, b = blockIdx.y;
    const float alpha = __ldg(alpha_p);

    if (t < 128) { s_pr[t] = prior_at(prior, b, h, t); s_bin[t] = b_in[t]; }
    __syncthreads();

    {   // sB <- Win padded (1152 uint4)
        const uint4* src = (const uint4*)g_WinP;
        uint4* dst = (uint4*)sB;
#pragma unroll
        for (int i = 0; i < 5; i++) {
            int idx = t + i * 256;
            if (idx < 1152) dst[idx] = src[idx];
        }
    }
    {   // sA <- F_mod bf16 [c][w]
        const float* xrow = x + b * 1048576 + h * 128;
#pragma unroll
        for (int i = 0; i < 16; i++) {
            int idx = t + i * 256;           // 4096 = 64c x 64 wp
            int c = idx >> 6, wp = (idx & 63) * 2;
            float2 f = *(const float2*)&xrow[c * 16384 + wp];
            f.x += alpha * s_pr[wp];
            f.y += alpha * s_pr[wp + 1];
            *(__nv_bfloat162*)&sA[c * LDA1 + wp] = __float22bfloat162_rn(f);
        }
    }
    __syncthreads();

    // MMA: warp wid owns m-rows w0..w0+15, full N=128, K=64
    const int w0 = wid * 16;
    float acc[16][4];
#pragma unroll
    for (int nt = 0; nt < 16; nt++)
#pragma unroll
        for (int j = 0; j < 4; j++) acc[nt][j] = 0.f;

    const uint32_t sA_u = smem_u32(sA), sB_u = smem_u32(sB);
    const int m_row = (lid & 7) + ((lid >> 4) << 3);
    const int m_col = ((lid >> 3) & 1) << 3;
    const uint32_t a_base = sA_u + (uint32_t)((m_row * LDA1 + w0 + m_col) * 2);
    const uint32_t b_base = sB_u + (uint32_t)((m_row * LDB1 + m_col) * 2);

#pragma unroll
    for (int ks = 0; ks < 4; ks++) {
        uint32_t afr[4];
        ldsm_x4_trans(afr, a_base + (uint32_t)(ks * 16 * LDA1 * 2));
#pragma unroll
        for (int np = 0; np < 8; np++) {     // 2 n-tiles per x4 B-load
            uint32_t bfr[4];
            ldsm_x4(bfr, b_base + (uint32_t)((np * 16 * LDB1 + ks * 16) * 2));
            mma_bf16(acc[2 * np],     afr, bfr);
            mma_bf16(acc[2 * np + 1], afr, bfr + 2);
        }
    }
    __syncthreads();   // frags in regs; overlay sPb

    {   // acc (+bias) -> sPb[o][w] bf16
        const int g = lid >> 2, q2 = (lid & 3) * 2;
        const int w = w0 + g;
#pragma unroll
        for (int nt = 0; nt < 16; nt++) {
            int o = nt * 8 + q2;
            sPb[o * LDS1 + w]           = __float2bfloat16(acc[nt][0] + s_bin[o]);
            sPb[(o + 1) * LDS1 + w]     = __float2bfloat16(acc[nt][1] + s_bin[o + 1]);
            sPb[o * LDS1 + w + 8]       = __float2bfloat16(acc[nt][2] + s_bin[o]);
            sPb[(o + 1) * LDS1 + w + 8] = __float2bfloat16(acc[nt][3] + s_bin[o + 1]);
        }
    }
    __syncthreads();

    {   // coalesced x_proj write-out (2048 uint4)
        __nv_bfloat16* xp = g_xp + (b * 128 + h) * 16384;
#pragma unroll
        for (int i = 0; i < 8; i++) {
            int idx = t + i * 256;
            int o = idx >> 4, c8 = (idx & 15) * 8;
            *(uint4*)&xp[o * 128 + c8] = *(const uint4*)&sPb[o * LDS1 + c8];
        }
    }
}

// ---- K2: per-(b,o) plane: concurrent h-scan + v-scan, merge, store ----
// smem: sX @0, sH @34816, sV @69632, each [128][136] bf16. total 104448B.
__global__ __launch_bounds__(256) void k2(const float* __restrict__ Bvec) {
    extern __shared__ __align__(16) char smch[];
    __nv_bfloat16* sX = (__nv_bfloat16*)smch;
    __nv_bfloat16* sH = (__nv_bfloat16*)(smch + 34816);
    __nv_bfloat16* sV = (__nv_bfloat16*)(smch + 69632);

    const int t = threadIdx.x;
    const int o = blockIdx.x, b = blockIdx.y;
    const float a = g_At[o], bv = __ldg(&Bvec[o]);
    const int gbase = b * 2097152 + o * 128;   // + h*16384 + w

    {   // load plane (2048 uint4)
        const __nv_bfloat16* src = g_xp + gbase;
#pragma unroll
        for (int i = 0; i < 8; i++) {
            int idx = t + i * 256;
            int h = idx >> 4, c8 = (idx & 15) * 8;
            *(uint4*)&sX[h * LDK2 + c8] = *(const uint4*)&src[h * 16384 + c8];
        }
    }
    __syncthreads();

    if (t < 128) {   // warps 0-3: h-scan row t -> sH
        const __nv_bfloat16* xr = &sX[t * LDK2];
        __nv_bfloat16* hr = &sH[t * LDK2];
        float st = 0.0f;
#pragma unroll 4
        for (int wb = 0; wb < 32; wb++) {
            uint2 u = *(const uint2*)&xr[wb * 4];
            float2 f0 = __bfloat1622float2(*(__nv_bfloat162*)&u.x);
            float2 f1 = __bfloat1622float2(*(__nv_bfloat162*)&u.y);
            st = fmaf(a, st, bv * f0.x); f0.x = st;
            st = fmaf(a, st, bv * f0.y); f0.y = st;
            st = fmaf(a, st, bv * f1.x); f1.x = st;
            st = fmaf(a, st, bv * f1.y); f1.y = st;
            __nv_bfloat162 p0 = __float22bfloat162_rn(f0);
            __nv_bfloat162 p1 = __float22bfloat162_rn(f1);
            *(uint2*)&hr[wb * 4] = make_uint2(*(uint32_t*)&p0, *(uint32_t*)&p1);
        }
    } else {         // warps 4-7: v-scan column w = t-128 -> sV
        const int w = t - 128;
        float st = 0.0f;
#pragma unroll 4
        for (int h = 0; h < 128; h++) {
            float xv = __bfloat162float(sX[h * LDK2 + w]);
            st = fmaf(a, st, bv * xv);
            sV[h * LDK2 + w] = __float2bfloat16(st);
        }
    }
    __syncthreads();

    {   // merge + store h_sum plane (2048 uint4)
        __nv_bfloat16* dst = g_hs + gbase;
#pragma unroll
        for (int i = 0; i < 8; i++) {
            int idx = t + i * 256;
            int h = idx >> 4, c8 = (idx & 15) * 8;
            uint4 uh = *(const uint4*)&sH[h * LDK2 + c8];
            uint4 uv = *(const uint4*)&sV[h * LDK2 + c8];
            uint4 r;
            *(__nv_bfloat162*)&r.x = __hadd2(*(__nv_bfloat162*)&uh.x, *(__nv_bfloat162*)&uv.x);
            *(__nv_bfloat162*)&r.y = __hadd2(*(__nv_bfloat162*)&uh.y, *(__nv_bfloat162*)&uv.y);
            *(__nv_bfloat162*)&r.z = __hadd2(*(__nv_bfloat162*)&uh.z, *(__nv_bfloat162*)&uv.z);
            *(__nv_bfloat162*)&r.w = __hadd2(*(__nv_bfloat162*)&uh.w, *(__nv_bfloat162*)&uv.w);
            *(uint4*)&dst[h * 16384 + c8] = r;
        }
    }
}

// ---- K3: per-(b,h): out = h_sum @ Wout^T (HMMA), fused fp32 epilogue ----
// smem: sA [128o][136w] bf16 34816B @0 ; sB [64c][136o] bf16 17408B @34816
//       sR [64c][132w] f32 33792B overlays sA after MMA.
__global__ __launch_bounds__(256) void k3(
    const float* __restrict__ x, const float* __restrict__ prior,
    const float* __restrict__ b_out, const float* __restrict__ alpha_p,
    const float* __restrict__ gamma_p, float* __restrict__ out)
{
    extern __shared__ __align__(16) char smch[];
    __nv_bfloat16* sA = (__nv_bfloat16*)smch;
    __nv_bfloat16* sB = (__nv_bfloat16*)(smch + 34816);
    float* sR = (float*)smch;
    __shared__ float s_pr[128], s_bo[64];

    const int t = threadIdx.x;
    const int wid = t >> 5, lid = t & 31;
    const int h = blockIdx.x, b = blockIdx.y;
    const float alpha = __ldg(alpha_p), gamma = __ldg(gamma_p);

    if (t < 128) s_pr[t] = prior_at(prior, b, h, t);
    if (t < 64) s_bo[t] = b_out[t];

    {   // sB <- Wout padded (1088 uint4)
        const uint4* src = (const uint4*)g_WoutP;
        uint4* dst = (uint4*)sB;
#pragma unroll
        for (int i = 0; i < 5; i++) {
            int idx = t + i * 256;
            if (idx < 1088) dst[idx] = src[idx];
        }
    }
    {   // sA <- h_sum [o][w]
        const __nv_bfloat16* hs = g_hs + (b * 128 + h) * 16384;
#pragma unroll
        for (int i = 0; i < 8; i++) {
            int idx = t + i * 256;           // 2048 = 128o x 16 w8
            int o = idx >> 4, w8 = (idx & 15) * 8;
            *(uint4*)&sA[o * LDA3 + w8] = *(const uint4*)&hs[o * 128 + w8];
        }
    }
    __syncthreads();

    // MMA: M=128(w) x N=64(c) x K=128(o)
    const int w0 = wid * 16;
    float acc[8][4];
#pragma unroll
    for (int nt = 0; nt < 8; nt++)
#pragma unroll
        for (int j = 0; j < 4; j++) acc[nt][j] = 0.f;

    const uint32_t sA_u = smem_u32(sA), sB_u = smem_u32(sB);
    const int m_row = (lid & 7) + ((lid >> 4) << 3);
    const int m_col = ((lid >> 3) & 1) << 3;
    const uint32_t a_base = sA_u + (uint32_t)((m_row * LDA3 + w0 + m_col) * 2);
    const uint32_t b_base = sB_u + (uint32_t)((m_row * LDB3 + m_col) * 2);

#pragma unroll
    for (int ks = 0; ks < 8; ks++) {
        uint32_t afr[4];
        ldsm_x4_trans(afr, a_base + (uint32_t)(ks * 16 * LDA3 * 2));
#pragma unroll
        for (int np = 0; np < 4; np++) {     // 2 n-tiles per x4 B-load
            uint32_t bfr[4];
            ldsm_x4(bfr, b_base + (uint32_t)((np * 16 * LDB3 + ks * 16) * 2));
            mma_bf16(acc[2 * np],     afr, bfr);
            mma_bf16(acc[2 * np + 1], afr, bfr + 2);
        }
    }
    __syncthreads();   // overlay sR

    {   // acc -> sR[c][w]
        const int g = lid >> 2, q2 = (lid & 3) * 2;
        const int w = w0 + g;
#pragma unroll
        for (int nt = 0; nt < 8; nt++) {
            int c = nt * 8 + q2;
            sR[c * LDP + w]           = acc[nt][0];
            sR[(c + 1) * LDP + w]     = acc[nt][1];
            sR[c * LDP + w + 8]       = acc[nt][2];
            sR[(c + 1) * LDP + w + 8] = acc[nt][3];
        }
    }
    __syncthreads();

    {   // fused epilogue, float4: out = x + alpha*pr + gamma*(res + b_out)
        const int base_bh = b * 1048576 + h * 128;
#pragma unroll
        for (int i = 0; i < 8; i++) {
            int idx = t + i * 256;           // 2048 = 64c x 32 w4
            int c = idx >> 5, w4 = (idx & 31) * 4;
            int gb = base_bh + c * 16384 + w4;
            float4 xv = *(const float4*)&x[gb];
            float4 rv = *(const float4*)&sR[c * LDP + w4];
            float4 pv = *(const float4*)&s_pr[w4];
            float bo = s_bo[c];
            float4 r;
            r.x = fmaf(alpha, pv.x, xv.x) + gamma * (rv.x + bo);
            r.y = fmaf(alpha, pv.y, xv.y) + gamma * (rv.y + bo);
            r.z = fmaf(alpha, pv.z, xv.z) + gamma * (rv.z + bo);
            r.w = fmaf(alpha, pv.w, xv.w) + gamma * (rv.w + bo);
            *(float4*)&out[gb] = r;
        }
    }
}

extern "C" void kernel_launch(void* const* d_in, const int* in_sizes, int n_in,
                              void* d_out, int out_size) {
    const float* x      = (const float*)d_in[0];
    const float* prior  = (const float*)d_in[1];
    const float* W_in   = (const float*)d_in[2];
    const float* b_in   = (const float*)d_in[3];
    const float* A      = (const float*)d_in[4];
    const float* B      = (const float*)d_in[5];
    const float* alpha  = (const float*)d_in[6];
    const float* gamma  = (const float*)d_in[7];
    const float* W_out  = (const float*)d_in[8];
    const float* b_out  = (const float*)d_in[9];
    float* out = (float*)d_out;

    const int smem_k1 = 35840;
    const int smem_k2 = 104448;
    const int smem_k3 = 34816 + 17408;   // 52224

    cudaFuncSetAttribute(k1, cudaFuncAttributeMaxDynamicSharedMemorySize, smem_k1);
    cudaFuncSetAttribute(k2, cudaFuncAttributeMaxDynamicSharedMemorySize, smem_k2);
    cudaFuncSetAttribute(k3, cudaFuncAttributeMaxDynamicSharedMemorySize, smem_k3);

    k_setup<<<32, 256>>>(W_in, W_out, A);
    dim3 grid(HDIM, BSZ);
    k1<<<grid, 256, smem_k1>>>(x, prior, b_in, alpha);
    k2<<<grid, 256, smem_k2>>>(B);
    k3<<<grid, 256, smem_k3>>>(x, prior, b_out, alpha, gamma, out);
}